// round 14
// baseline (speedup 1.0000x reference)
#include <cuda_runtime.h>
#include <cstdint>

#define GN 100000
#define GE 1600000
#define H0 32
#define H1 8

// K1 grid layout (128 threads/block)
#define NG 391    // gemm blocks: 391*256 rows
#define NZ 782    // hacc-zero blocks: 782*1024 float4 >= 800,000
#define NC 3125   // edge-cvt blocks: 3125*512 = 1.6M edges
#define K1_GRID (NG + NZ + NC + 1)

// ---------------- scratch (static __device__ — no allocations) ----------------
// Zero-invariant buffers (module-load zero; every run resets them in k_oinit):
__device__ int   g_cnt[GN];      // in-edge counts (deg = 1 + cnt)
__device__ float g_wsum[GN];     // masked-weight sum (deg2 = 1 + wsum)

__device__ __align__(16) float g_xw[GN * H0];    // x @ W0
__device__ __align__(16) float g_hacc[GN * H0];  // conv1 edge aggregation
__device__ __align__(16) float g_out[GN * H1];   // conv2 result (no atomics on d_out)
__device__ __align__(16) float g_hw[GN * H1];    // h @ W1
__device__ __align__(16) int2  g_eidx[GE];       // packed (row, col) int32
__device__ float g_dinv2[GN];
__device__ float g_s1[GN];
__device__ float g_s2[GN];
__device__ float g_mw[GE];       // masked edge weight
__device__ float g_wa1[H0];
__device__ float g_wa2[H0];
__device__ float g_cbias;

// ---------------- helpers ----------------
__device__ __forceinline__ void red4(float* a, float x, float y, float z, float w) {
    asm volatile(
        "{\n\t"
        ".reg .u64 p;\n\t"
        "cvta.to.global.u64 p, %0;\n\t"
        "red.global.add.v4.f32 [p], {%1,%2,%3,%4};\n\t"
        "}"
        :: "l"(a), "f"(x), "f"(y), "f"(z), "f"(w) : "memory");
}

__device__ __forceinline__ float tf32r(float a) {
    float r;
    asm("cvt.rna.tf32.f32 %0, %1;" : "=f"(r) : "f"(a));
    return r;
}

__device__ __forceinline__ void mma_tf32(float* c, uint32_t a0, uint32_t a1,
                                         uint32_t a2, uint32_t a3,
                                         uint32_t b0, uint32_t b1) {
    asm("mma.sync.aligned.m16n8k8.row.col.f32.tf32.tf32.f32 "
        "{%0,%1,%2,%3},{%4,%5,%6,%7},{%8,%9},{%0,%1,%2,%3};"
        : "+f"(c[0]), "+f"(c[1]), "+f"(c[2]), "+f"(c[3])
        : "r"(a0), "r"(a1), "r"(a2), "r"(a3), "r"(b0), "r"(b1));
}

// ---------------- K1: gemm || hacc-zero || edge-cvt || weight-precompute ----------
#define SXP 36
#define SWP 33
__global__ __launch_bounds__(128) void k_mega(
        const float* __restrict__ x, const float* __restrict__ W0,
        const void* __restrict__ ei,
        const float* __restrict__ Wnb, const float* __restrict__ bnb,
        const float* __restrict__ Wself, const float* __restrict__ bself,
        const float* __restrict__ Watt, const float* __restrict__ batt) {
    __shared__ __align__(16) float sX[256 * SXP];  // 36.9KB
    __shared__ __align__(16) float sW[32 * SWP];   // 4.2KB
    const int tid = threadIdx.x;
    const int bid = blockIdx.x;

    if (bid < NG) {
        // ---- tf32 tensor-core GEMM: 256 rows x 32 cols per block ----
        const int lane = tid & 31;
        const int gid = lane >> 2;
        const int tg = lane & 3;
        const int mbase = (tid >> 5) * 64;
        const int rbase = bid * 256;

        float c[4][4][4];
#pragma unroll
        for (int mt = 0; mt < 4; mt++)
#pragma unroll
            for (int t = 0; t < 4; t++)
#pragma unroll
                for (int r = 0; r < 4; r++) c[mt][t][r] = 0.f;

        for (int k0 = 0; k0 < 512; k0 += 32) {
#pragma unroll
            for (int i = 0; i < 16; i++) {
                int idx = tid + 128 * i;
                int row = idx >> 3, q = idx & 7;
                int grow = rbase + row;
                if (grow >= GN) grow = GN - 1;
                float4 v = *reinterpret_cast<const float4*>(
                    x + (size_t)grow * 512 + k0 + 4 * q);
                v.x = tf32r(v.x); v.y = tf32r(v.y); v.z = tf32r(v.z); v.w = tf32r(v.w);
                *reinterpret_cast<float4*>(&sX[row * SXP + 4 * q]) = v;
            }
#pragma unroll
            for (int i = 0; i < 8; i++) {
                int idx = tid + 128 * i;
                int kk = idx >> 5, cc = idx & 31;
                sW[kk * SWP + cc] = tf32r(W0[(k0 + kk) * H0 + cc]);
            }
            __syncthreads();

#pragma unroll
            for (int kk = 0; kk < 4; kk++) {
                uint32_t b[4][2];
#pragma unroll
                for (int t = 0; t < 4; t++) {
                    b[t][0] = __float_as_uint(sW[(kk * 8 + tg) * SWP + t * 8 + gid]);
                    b[t][1] = __float_as_uint(sW[(kk * 8 + tg + 4) * SWP + t * 8 + gid]);
                }
#pragma unroll
                for (int mt = 0; mt < 4; mt++) {
                    int r0 = mbase + mt * 16;
                    uint32_t a0 = __float_as_uint(sX[(r0 + gid) * SXP + kk * 8 + tg]);
                    uint32_t a1 = __float_as_uint(sX[(r0 + gid + 8) * SXP + kk * 8 + tg]);
                    uint32_t a2 = __float_as_uint(sX[(r0 + gid) * SXP + kk * 8 + tg + 4]);
                    uint32_t a3 = __float_as_uint(sX[(r0 + gid + 8) * SXP + kk * 8 + tg + 4]);
#pragma unroll
                    for (int t = 0; t < 4; t++)
                        mma_tf32(c[mt][t], a0, a1, a2, a3, b[t][0], b[t][1]);
                }
            }
            __syncthreads();
        }

#pragma unroll
        for (int mt = 0; mt < 4; mt++) {
            int r = rbase + mbase + mt * 16 + gid;
#pragma unroll
            for (int t = 0; t < 4; t++) {
                int col = t * 8 + 2 * tg;
                if (r < GN)
                    *reinterpret_cast<float2*>(&g_xw[r * H0 + col]) =
                        make_float2(c[mt][t][0], c[mt][t][1]);
                if (r + 8 < GN)
                    *reinterpret_cast<float2*>(&g_xw[(r + 8) * H0 + col]) =
                        make_float2(c[mt][t][2], c[mt][t][3]);
            }
        }
    } else if (bid < NG + NZ) {
        // ---- zero g_hacc (float4 stores) ----
        int zb = bid - NG;
        float4* h4 = reinterpret_cast<float4*>(g_hacc);
        const float4 z = make_float4(0.f, 0.f, 0.f, 0.f);
#pragma unroll
        for (int k = 0; k < 8; k++) {
            int idx = zb * 1024 + tid + 128 * k;
            if (idx < GN * H0 / 4) h4[idx] = z;
        }
    } else if (bid < NG + NZ + NC) {
        // ---- edge convert + count histogram ----
        // dtype detect: int64 (LE) => odd 32-bit words of the first 256 are all 0.
        // Each warp ballots its 32 sampled odd words; any warp seeing nonzero
        // clears the shared flag (benign same-value race), then all read it.
        __shared__ int s64;
        const unsigned int* w = (const unsigned int*)ei;
        unsigned int myw = w[2 * tid + 1];
        unsigned int any = __ballot_sync(0xFFFFFFFFu, myw != 0u);
        if (tid == 0) s64 = 1;
        __syncthreads();
        if (any != 0u) s64 = 0;
        __syncthreads();
        int is64 = s64;

        int eb = bid - NG - NZ;
#pragma unroll
        for (int j = 0; j < 4; j++) {
            int e = eb * 512 + tid + 128 * j;
            if (e < GE) {
                int r, c;
                if (is64) {
                    r = (int)((const long long*)ei)[e];
                    c = (int)((const long long*)ei)[GE + e];
                } else {
                    r = ((const int*)ei)[e];
                    c = ((const int*)ei)[GE + e];
                }
                g_eidx[e] = make_int2(r, c);
                atomicAdd(&g_cnt[c], 1);
            }
        }
    } else {
        // ---- attention collapse precompute ----
        if (tid < H0) {
            float a1 = 0.f, a2 = 0.f;
#pragma unroll
            for (int k = 0; k < 8; k++) {
                a1 += Wnb[tid * 8 + k] * Watt[k];
                a2 += Wself[tid * 8 + k] * Watt[8 + k];
            }
            g_wa1[tid] = a1;
            g_wa2[tid] = a2;
        }
        if (tid == H0) {
            float c = batt[0];
            for (int k = 0; k < 8; k++) c += bnb[k] * Watt[k] + bself[k] * Watt[8 + k];
            g_cbias = c;
        }
    }
}

// ---------------- conv1 aggregation: 8 lanes/edge, scalar work deduped ------------
__global__ __launch_bounds__(256) void k_agg1() {
    long long t = (long long)blockIdx.x * blockDim.x + threadIdx.x;
    if (t >= (long long)GE * 8) return;
    int e = (int)(t >> 3);
    int sub = (int)(t & 7);
    int lane = threadIdx.x & 31;
    int lead = lane & ~7;

    int row = 0, col = 0;
    float norm = 0.f;
    if ((lane & 7) == 0) {
        int2 rc = g_eidx[e];
        row = rc.x; col = rc.y;
        norm = rsqrtf((1.f + (float)g_cnt[row]) * (1.f + (float)g_cnt[col]));
    }
    row  = __shfl_sync(0xFFFFFFFFu, row, lead);
    col  = __shfl_sync(0xFFFFFFFFu, col, lead);
    norm = __shfl_sync(0xFFFFFFFFu, norm, lead);

    float4 v = *reinterpret_cast<const float4*>(&g_xw[row * H0 + sub * 4]);
    red4(&g_hacc[col * H0 + sub * 4], v.x * norm, v.y * norm, v.z * norm, v.w * norm);
}

// ---------------- per-node: h, s1, s2, hw = h @ W1 (warp per node) ----------------
__global__ void k_node(const float* __restrict__ b0, const float* __restrict__ W1) {
    int node = (blockIdx.x * blockDim.x + threadIdx.x) >> 5;
    int lane = threadIdx.x & 31;
    if (node >= GN) return;

    float di2 = 1.0f / (1.f + (float)g_cnt[node]);   // dinv1^2 (self-loop term)
    float h = g_hacc[node * H0 + lane] + g_xw[node * H0 + lane] * di2 + b0[lane];

    float p1 = h * g_wa1[lane];
    float p2 = h * g_wa2[lane];
#pragma unroll
    for (int o = 16; o; o >>= 1) {
        p1 += __shfl_xor_sync(0xFFFFFFFFu, p1, o);
        p2 += __shfl_xor_sync(0xFFFFFFFFu, p2, o);
    }
    if (lane == 0) { g_s1[node] = p1; g_s2[node] = p2; }

    float4 wA = *reinterpret_cast<const float4*>(W1 + lane * 8);
    float4 wB = *reinterpret_cast<const float4*>(W1 + lane * 8 + 4);
    float o0 = h * wA.x, o1 = h * wA.y, o2 = h * wA.z, o3 = h * wA.w;
    float o4 = h * wB.x, o5 = h * wB.y, o6 = h * wB.z, o7 = h * wB.w;
#pragma unroll
    for (int o = 16; o; o >>= 1) {
        o0 += __shfl_xor_sync(0xFFFFFFFFu, o0, o);
        o1 += __shfl_xor_sync(0xFFFFFFFFu, o1, o);
        o2 += __shfl_xor_sync(0xFFFFFFFFu, o2, o);
        o3 += __shfl_xor_sync(0xFFFFFFFFu, o3, o);
        o4 += __shfl_xor_sync(0xFFFFFFFFu, o4, o);
        o5 += __shfl_xor_sync(0xFFFFFFFFu, o5, o);
        o6 += __shfl_xor_sync(0xFFFFFFFFu, o6, o);
        o7 += __shfl_xor_sync(0xFFFFFFFFu, o7, o);
    }
    if (lane == 0) {
        float4* hw4 = reinterpret_cast<float4*>(&g_hw[node * H1]);
        hw4[0] = make_float4(o0, o1, o2, o3);
        hw4[1] = make_float4(o4, o5, o6, o7);
    }
}

// ---------------- edge gate: mw + wsum (zero-invariant accumulator) ---------------
__global__ void k_gate() {
    int e = blockIdx.x * blockDim.x + threadIdx.x;
    if (e >= GE) return;
    int2 rc = g_eidx[e];
    float w = g_s1[rc.x] + g_s2[rc.y] + g_cbias;
    float mw = 0.f;
    if (w > 0.f) {
        float s = 1.f / (1.f + __expf(-w));       // sigmoid(relu(w)), w>0
        float mask = fminf(s * 1.01f, 1.f);       // clip(s*(zeta-gamma)+gamma, 0, 1)
        mw = mask * w;
        atomicAdd(&g_wsum[rc.y], mw);
    }
    g_mw[e] = mw;
}

// ---------------- oinit: dinv2, g_out base; reset zero-invariant buffers ----------
__global__ void k_oinit(const float* __restrict__ b1) {
    int node = blockIdx.x * blockDim.x + threadIdx.x;
    if (node >= GN) return;
    float d = rsqrtf(1.f + g_wsum[node]);
    g_dinv2[node] = d;
    g_wsum[node] = 0.f;   // reset for next graph replay
    g_cnt[node] = 0;      // reset for next graph replay
    float dd = d * d;
    float4 hw0 = *reinterpret_cast<const float4*>(&g_hw[node * H1]);
    float4 hw1 = *reinterpret_cast<const float4*>(&g_hw[node * H1 + 4]);
    float4 bA = *reinterpret_cast<const float4*>(b1);
    float4 bB = *reinterpret_cast<const float4*>(b1 + 4);
    float4 o0 = make_float4(hw0.x * dd + bA.x, hw0.y * dd + bA.y,
                            hw0.z * dd + bA.z, hw0.w * dd + bA.w);
    float4 o1 = make_float4(hw1.x * dd + bB.x, hw1.y * dd + bB.y,
                            hw1.z * dd + bB.z, hw1.w * dd + bB.w);
    *reinterpret_cast<float4*>(&g_out[node * H1]) = o0;
    *reinterpret_cast<float4*>(&g_out[node * H1 + 4]) = o1;
}

// ---------------- conv2 aggregation: 2 threads / edge, RED.128 ----------------
__global__ void k_agg2() {
    long long t = (long long)blockIdx.x * blockDim.x + threadIdx.x;
    if (t >= (long long)GE * 2) return;
    int e = (int)(t >> 1), q = (int)(t & 1);
    float mw = g_mw[e];
    if (mw == 0.f) return;
    int2 rc = g_eidx[e];
    float norm = g_dinv2[rc.x] * mw * g_dinv2[rc.y];
    float4 v = *reinterpret_cast<const float4*>(&g_hw[rc.x * H1 + q * 4]);
    red4(&g_out[rc.y * H1 + q * 4], v.x * norm, v.y * norm, v.z * norm, v.w * norm);
}

// ---------------- final copy ----------------
__global__ void k_final(float* __restrict__ out) {
    int i = blockIdx.x * blockDim.x + threadIdx.x;
    if (i < GN * H1 / 4) {
        reinterpret_cast<float4*>(out)[i] = reinterpret_cast<const float4*>(g_out)[i];
    }
}

// ---------------- launch ----------------
extern "C" void kernel_launch(void* const* d_in, const int* in_sizes, int n_in,
                              void* d_out, int out_size) {
    const float* x   = (const float*)d_in[0];
    const void*  ei  = d_in[1];
    const float* W0  = (const float*)d_in[2];
    const float* b0  = (const float*)d_in[3];
    const float* W1  = (const float*)d_in[4];
    const float* b1  = (const float*)d_in[5];
    const float* Wnb = (const float*)d_in[6];
    const float* bnb = (const float*)d_in[7];
    const float* Wself = (const float*)d_in[8];
    const float* bself = (const float*)d_in[9];
    const float* Watt  = (const float*)d_in[10];
    const float* batt  = (const float*)d_in[11];
    float* out = (float*)d_out;

    k_mega<<<K1_GRID, 128>>>(x, W0, ei, Wnb, bnb, Wself, bself, Watt, batt);
    k_agg1<<<(GE * 8 + 255) / 256, 256>>>();
    k_node<<<(GN * 32 + 255) / 256, 256>>>(b0, W1);
    k_gate<<<(GE + 255) / 256, 256>>>();
    k_oinit<<<(GN + 255) / 256, 256>>>(b1);
    k_agg2<<<(GE * 2 + 255) / 256, 256>>>();
    k_final<<<(GN * H1 / 4 + 255) / 256, 256>>>(out);
}

// round 15
// speedup vs baseline: 1.4921x; 1.4921x over previous
#include <cuda_runtime.h>
#include <cstdint>

#define GN 100000
#define GE 1600000
#define H0 32
#define H1 8

// ---------------- scratch (static __device__ — no allocations) ----------------
__device__ __align__(16) float g_xw[GN * H0];    // x @ W0
__device__ __align__(16) float g_hacc[GN * H0];  // conv1 edge aggregation
__device__ __align__(16) float g_hw[GN * H1];    // h @ W1
__device__ __align__(16) int2  g_eidx[GE];       // packed (row, col) int32
__device__ float g_deg1[GN];       // raw degree (1 + count)
__device__ float g_deg2[GN];       // masked-weight degree -> dinv2 (in place)
__device__ float g_s1[GN];
__device__ float g_s2[GN];
__device__ float g_mw[GE];         // masked edge weight
__device__ float g_wa1[H0];
__device__ float g_wa2[H0];
__device__ float g_cbias;
__device__ int   g_is64;

// ---------------- helpers ----------------
__device__ __forceinline__ void red4(float* a, float x, float y, float z, float w) {
    asm volatile(
        "{\n\t"
        ".reg .u64 p;\n\t"
        "cvta.to.global.u64 p, %0;\n\t"
        "red.global.add.v4.f32 [p], {%1,%2,%3,%4};\n\t"
        "}"
        :: "l"(a), "f"(x), "f"(y), "f"(z), "f"(w) : "memory");
}

__device__ __forceinline__ int eidx(const void* ei, long long i) {
    if (g_is64) return (int)((const long long*)ei)[i];
    return ((const int*)ei)[i];
}

__device__ __forceinline__ float tf32r(float a) {
    float r;
    asm("cvt.rna.tf32.f32 %0, %1;" : "=f"(r) : "f"(a));
    return r;
}

__device__ __forceinline__ void mma_tf32(float* c, uint32_t a0, uint32_t a1,
                                         uint32_t a2, uint32_t a3,
                                         uint32_t b0, uint32_t b1) {
    asm("mma.sync.aligned.m16n8k8.row.col.f32.tf32.tf32.f32 "
        "{%0,%1,%2,%3},{%4,%5,%6,%7},{%8,%9},{%0,%1,%2,%3};"
        : "+f"(c[0]), "+f"(c[1]), "+f"(c[2]), "+f"(c[3])
        : "r"(a0), "r"(a1), "r"(a2), "r"(a3), "r"(b0), "r"(b1));
}

// ---------------- fused setup ----------------
__global__ void k_setup(const unsigned int* __restrict__ eiw,
                        const float* __restrict__ Wnb, const float* __restrict__ bnb,
                        const float* __restrict__ Wself, const float* __restrict__ bself,
                        const float* __restrict__ Watt, const float* __restrict__ batt) {
    int i = blockIdx.x * blockDim.x + threadIdx.x;
    if (i < GN * H0) g_hacc[i] = 0.f;
    if (i < GN) { g_deg1[i] = 1.f; g_deg2[i] = 1.f; }  // self-loop weight 1
    if (i < H0) {
        float a1 = 0.f, a2 = 0.f;
#pragma unroll
        for (int k = 0; k < 8; k++) {
            a1 += Wnb[i * 8 + k] * Watt[k];
            a2 += Wself[i * 8 + k] * Watt[8 + k];
        }
        g_wa1[i] = a1;
        g_wa2[i] = a2;
    }
    if (i == H0) {
        float c = batt[0];
        for (int k = 0; k < 8; k++) c += bnb[k] * Watt[k] + bself[k] * Watt[8 + k];
        g_cbias = c;
    }
    if (i == H0 + 1) {
        // edge values < 2^17: if int64 (LE), every odd 32-bit word is 0
        int all0 = 1;
        for (int j = 1; j < 512; j += 2)
            if (eiw[j] != 0u) { all0 = 0; break; }
        g_is64 = all0;
    }
}

// ---------------- GEMM: xw = x @ W0, tf32 tensor cores ----------------
#define SXP 36
#define SWP 33
__global__ __launch_bounds__(128) void k_gemm(const float* __restrict__ x,
                                              const float* __restrict__ W0) {
    __shared__ __align__(16) float sX[256 * SXP];  // 36.9KB (tf32-rounded)
    __shared__ __align__(16) float sW[32 * SWP];   // 4.2KB

    const int tid = threadIdx.x;
    const int lane = tid & 31;
    const int gid = lane >> 2;
    const int tg = lane & 3;
    const int mbase = (tid >> 5) * 64;
    const int rbase = blockIdx.x * 256;

    float c[4][4][4];
#pragma unroll
    for (int mt = 0; mt < 4; mt++)
#pragma unroll
        for (int t = 0; t < 4; t++)
#pragma unroll
            for (int r = 0; r < 4; r++) c[mt][t][r] = 0.f;

    for (int k0 = 0; k0 < 512; k0 += 32) {
#pragma unroll
        for (int i = 0; i < 16; i++) {
            int idx = tid + 128 * i;
            int row = idx >> 3, q = idx & 7;
            int grow = rbase + row;
            if (grow >= GN) grow = GN - 1;
            float4 v = *reinterpret_cast<const float4*>(
                x + (size_t)grow * 512 + k0 + 4 * q);
            v.x = tf32r(v.x); v.y = tf32r(v.y); v.z = tf32r(v.z); v.w = tf32r(v.w);
            *reinterpret_cast<float4*>(&sX[row * SXP + 4 * q]) = v;
        }
#pragma unroll
        for (int i = 0; i < 8; i++) {
            int idx = tid + 128 * i;
            int kk = idx >> 5, cc = idx & 31;
            sW[kk * SWP + cc] = tf32r(W0[(k0 + kk) * H0 + cc]);
        }
        __syncthreads();

#pragma unroll
        for (int kk = 0; kk < 4; kk++) {
            uint32_t b[4][2];
#pragma unroll
            for (int t = 0; t < 4; t++) {
                b[t][0] = __float_as_uint(sW[(kk * 8 + tg) * SWP + t * 8 + gid]);
                b[t][1] = __float_as_uint(sW[(kk * 8 + tg + 4) * SWP + t * 8 + gid]);
            }
#pragma unroll
            for (int mt = 0; mt < 4; mt++) {
                int r0 = mbase + mt * 16;
                uint32_t a0 = __float_as_uint(sX[(r0 + gid) * SXP + kk * 8 + tg]);
                uint32_t a1 = __float_as_uint(sX[(r0 + gid + 8) * SXP + kk * 8 + tg]);
                uint32_t a2 = __float_as_uint(sX[(r0 + gid) * SXP + kk * 8 + tg + 4]);
                uint32_t a3 = __float_as_uint(sX[(r0 + gid + 8) * SXP + kk * 8 + tg + 4]);
#pragma unroll
                for (int t = 0; t < 4; t++)
                    mma_tf32(c[mt][t], a0, a1, a2, a3, b[t][0], b[t][1]);
            }
        }
        __syncthreads();
    }

#pragma unroll
    for (int mt = 0; mt < 4; mt++) {
        int r = rbase + mbase + mt * 16 + gid;
#pragma unroll
        for (int t = 0; t < 4; t++) {
            int col = t * 8 + 2 * tg;
            if (r < GN)
                *reinterpret_cast<float2*>(&g_xw[r * H0 + col]) =
                    make_float2(c[mt][t][0], c[mt][t][1]);
            if (r + 8 < GN)
                *reinterpret_cast<float2*>(&g_xw[(r + 8) * H0 + col]) =
                    make_float2(c[mt][t][2], c[mt][t][3]);
        }
    }
}

// ---------------- edge conversion to packed int2 + degree histogram ----------------
__global__ void k_cvtdeg(const void* __restrict__ ei) {
    int e = blockIdx.x * blockDim.x + threadIdx.x;
    if (e >= GE) return;
    int r = eidx(ei, e);
    int c = eidx(ei, (long long)GE + e);
    g_eidx[e] = make_int2(r, c);
    atomicAdd(&g_deg1[c], 1.0f);
}

// ---------------- conv1 aggregation: 8 lanes/edge, scalar work deduped ------------
__global__ __launch_bounds__(256) void k_agg1() {
    long long t = (long long)blockIdx.x * blockDim.x + threadIdx.x;
    if (t >= (long long)GE * 8) return;
    int e = (int)(t >> 3);
    int sub = (int)(t & 7);
    int lane = threadIdx.x & 31;
    int lead = lane & ~7;          // first lane of this 8-lane group

    int row = 0, col = 0;
    float norm = 0.f;
    if ((lane & 7) == 0) {
        int2 rc = g_eidx[e];
        row = rc.x; col = rc.y;
        norm = rsqrtf(g_deg1[row] * g_deg1[col]);
    }
    row  = __shfl_sync(0xFFFFFFFFu, row, lead);
    col  = __shfl_sync(0xFFFFFFFFu, col, lead);
    norm = __shfl_sync(0xFFFFFFFFu, norm, lead);

    float4 v = *reinterpret_cast<const float4*>(&g_xw[row * H0 + sub * 4]);
    red4(&g_hacc[col * H0 + sub * 4], v.x * norm, v.y * norm, v.z * norm, v.w * norm);
}

// ---------------- per-node: h, s1, s2, hw = h @ W1 (warp per node) ----------------
__global__ void k_node(const float* __restrict__ b0, const float* __restrict__ W1) {
    int node = (blockIdx.x * blockDim.x + threadIdx.x) >> 5;
    int lane = threadIdx.x & 31;
    if (node >= GN) return;

    float di2 = 1.0f / g_deg1[node];   // dinv1^2 for the self-loop term
    float h = g_hacc[node * H0 + lane] + g_xw[node * H0 + lane] * di2 + b0[lane];

    float p1 = h * g_wa1[lane];
    float p2 = h * g_wa2[lane];
#pragma unroll
    for (int o = 16; o; o >>= 1) {
        p1 += __shfl_xor_sync(0xFFFFFFFFu, p1, o);
        p2 += __shfl_xor_sync(0xFFFFFFFFu, p2, o);
    }
    if (lane == 0) { g_s1[node] = p1; g_s2[node] = p2; }

    float4 wA = *reinterpret_cast<const float4*>(W1 + lane * 8);
    float4 wB = *reinterpret_cast<const float4*>(W1 + lane * 8 + 4);
    float o0 = h * wA.x, o1 = h * wA.y, o2 = h * wA.z, o3 = h * wA.w;
    float o4 = h * wB.x, o5 = h * wB.y, o6 = h * wB.z, o7 = h * wB.w;
#pragma unroll
    for (int o = 16; o; o >>= 1) {
        o0 += __shfl_xor_sync(0xFFFFFFFFu, o0, o);
        o1 += __shfl_xor_sync(0xFFFFFFFFu, o1, o);
        o2 += __shfl_xor_sync(0xFFFFFFFFu, o2, o);
        o3 += __shfl_xor_sync(0xFFFFFFFFu, o3, o);
        o4 += __shfl_xor_sync(0xFFFFFFFFu, o4, o);
        o5 += __shfl_xor_sync(0xFFFFFFFFu, o5, o);
        o6 += __shfl_xor_sync(0xFFFFFFFFu, o6, o);
        o7 += __shfl_xor_sync(0xFFFFFFFFu, o7, o);
    }
    if (lane == 0) {
        float4* hw4 = reinterpret_cast<float4*>(&g_hw[node * H1]);
        hw4[0] = make_float4(o0, o1, o2, o3);
        hw4[1] = make_float4(o4, o5, o6, o7);
    }
}

// ---------------- edge gate + deg2 ----------------
__global__ void k_gate() {
    int e = blockIdx.x * blockDim.x + threadIdx.x;
    if (e >= GE) return;
    int2 rc = g_eidx[e];
    float w = g_s1[rc.x] + g_s2[rc.y] + g_cbias;  // pre-relu attention logit
    float mw = 0.f;
    if (w > 0.f) {
        float s = 1.f / (1.f + __expf(-w));       // sigmoid(relu(w)), w>0
        float mask = fminf(s * 1.01f, 1.f);       // clip(s*(zeta-gamma)+gamma, 0, 1)
        mw = mask * w;
        atomicAdd(&g_deg2[rc.y], mw);
    }
    g_mw[e] = mw;
}

// ---------------- rsq2 + out base (thread per node, plain stores to d_out) --------
__global__ void k_oinit(float* __restrict__ out, const float* __restrict__ b1) {
    int node = blockIdx.x * blockDim.x + threadIdx.x;
    if (node >= GN) return;
    float d = rsqrtf(g_deg2[node]);
    g_deg2[node] = d;           // dinv2 for agg2
    float dd = d * d;
    float4 hw0 = *reinterpret_cast<const float4*>(&g_hw[node * H1]);
    float4 hw1 = *reinterpret_cast<const float4*>(&g_hw[node * H1 + 4]);
    float4 bA = *reinterpret_cast<const float4*>(b1);
    float4 bB = *reinterpret_cast<const float4*>(b1 + 4);
    float4 o0 = make_float4(hw0.x * dd + bA.x, hw0.y * dd + bA.y,
                            hw0.z * dd + bA.z, hw0.w * dd + bA.w);
    float4 o1 = make_float4(hw1.x * dd + bB.x, hw1.y * dd + bB.y,
                            hw1.z * dd + bB.z, hw1.w * dd + bB.w);
    *reinterpret_cast<float4*>(&out[node * H1]) = o0;
    *reinterpret_cast<float4*>(&out[node * H1 + 4]) = o1;
}

// ---------------- conv2 aggregation: 2 threads / edge, RED.128 into d_out ---------
__global__ void k_agg2(float* __restrict__ out) {
    long long t = (long long)blockIdx.x * blockDim.x + threadIdx.x;
    if (t >= (long long)GE * 2) return;
    int e = (int)(t >> 1), q = (int)(t & 1);
    float mw = g_mw[e];
    if (mw == 0.f) return;  // gated off: exact zero contribution
    int2 rc = g_eidx[e];
    float norm = g_deg2[rc.x] * mw * g_deg2[rc.y];
    float4 v = *reinterpret_cast<const float4*>(&g_hw[rc.x * H1 + q * 4]);
    red4(&out[rc.y * H1 + q * 4], v.x * norm, v.y * norm, v.z * norm, v.w * norm);
}

// ---------------- launch ----------------
extern "C" void kernel_launch(void* const* d_in, const int* in_sizes, int n_in,
                              void* d_out, int out_size) {
    const float* x   = (const float*)d_in[0];
    const void*  ei  = d_in[1];
    const float* W0  = (const float*)d_in[2];
    const float* b0  = (const float*)d_in[3];
    const float* W1  = (const float*)d_in[4];
    const float* b1  = (const float*)d_in[5];
    const float* Wnb = (const float*)d_in[6];
    const float* bnb = (const float*)d_in[7];
    const float* Wself = (const float*)d_in[8];
    const float* bself = (const float*)d_in[9];
    const float* Watt  = (const float*)d_in[10];
    const float* batt  = (const float*)d_in[11];
    float* out = (float*)d_out;

    k_setup<<<(GN * H0 + 255) / 256, 256>>>((const unsigned int*)ei,
                                            Wnb, bnb, Wself, bself, Watt, batt);
    k_gemm<<<(GN + 255) / 256, 128>>>(x, W0);
    k_cvtdeg<<<(GE + 255) / 256, 256>>>(ei);
    k_agg1<<<(GE * 8 + 255) / 256, 256>>>();
    k_node<<<(GN * 32 + 255) / 256, 256>>>(b0, W1);
    k_gate<<<(GE + 255) / 256, 256>>>();
    k_oinit<<<(GN + 255) / 256, 256>>>(out, b1);
    k_agg2<<<(GE * 2 + 255) / 256, 256>>>(out);
}

// round 16
// speedup vs baseline: 1.4996x; 1.0050x over previous
#include <cuda_runtime.h>
#include <cstdint>

#define GN 100000
#define GE 1600000
#define H0 32
#define H1 8

// ---------------- scratch (static __device__ — no allocations) ----------------
__device__ __align__(16) float g_xw[GN * H0];    // (x @ W0) * dinv1[row]  (pre-scaled)
__device__ __align__(16) float g_hacc[GN * H0];  // conv1 edge aggregation (unscaled sum)
__device__ __align__(16) float g_hw[GN * H1];    // h @ W1 (scaled by dinv2 in oinit)
__device__ __align__(16) int2  g_eidx[GE];       // packed (row, col) int32
__device__ float g_deg1[GN];       // raw degree (1 + count)
__device__ float g_deg2[GN];       // masked-weight degree -> dinv2 (in place)
__device__ float g_s1[GN];
__device__ float g_s2[GN];
__device__ float g_mw[GE];         // masked edge weight
__device__ float g_wa1[H0];
__device__ float g_wa2[H0];
__device__ float g_cbias;
__device__ int   g_is64;

// ---------------- helpers ----------------
__device__ __forceinline__ void red4(float* a, float x, float y, float z, float w) {
    asm volatile(
        "{\n\t"
        ".reg .u64 p;\n\t"
        "cvta.to.global.u64 p, %0;\n\t"
        "red.global.add.v4.f32 [p], {%1,%2,%3,%4};\n\t"
        "}"
        :: "l"(a), "f"(x), "f"(y), "f"(z), "f"(w) : "memory");
}

__device__ __forceinline__ int eidx(const void* ei, long long i) {
    if (g_is64) return (int)((const long long*)ei)[i];
    return ((const int*)ei)[i];
}

__device__ __forceinline__ float tf32r(float a) {
    float r;
    asm("cvt.rna.tf32.f32 %0, %1;" : "=f"(r) : "f"(a));
    return r;
}

__device__ __forceinline__ void mma_tf32(float* c, uint32_t a0, uint32_t a1,
                                         uint32_t a2, uint32_t a3,
                                         uint32_t b0, uint32_t b1) {
    asm("mma.sync.aligned.m16n8k8.row.col.f32.tf32.tf32.f32 "
        "{%0,%1,%2,%3},{%4,%5,%6,%7},{%8,%9},{%0,%1,%2,%3};"
        : "+f"(c[0]), "+f"(c[1]), "+f"(c[2]), "+f"(c[3])
        : "r"(a0), "r"(a1), "r"(a2), "r"(a3), "r"(b0), "r"(b1));
}

// ---------------- fused setup ----------------
__global__ void k_setup(const unsigned int* __restrict__ eiw,
                        const float* __restrict__ Wnb, const float* __restrict__ bnb,
                        const float* __restrict__ Wself, const float* __restrict__ bself,
                        const float* __restrict__ Watt, const float* __restrict__ batt) {
    int i = blockIdx.x * blockDim.x + threadIdx.x;
    if (i < GN * H0) g_hacc[i] = 0.f;
    if (i < GN) { g_deg1[i] = 1.f; g_deg2[i] = 1.f; }  // self-loop weight 1
    if (i < H0) {
        float a1 = 0.f, a2 = 0.f;
#pragma unroll
        for (int k = 0; k < 8; k++) {
            a1 += Wnb[i * 8 + k] * Watt[k];
            a2 += Wself[i * 8 + k] * Watt[8 + k];
        }
        g_wa1[i] = a1;
        g_wa2[i] = a2;
    }
    if (i == H0) {
        float c = batt[0];
        for (int k = 0; k < 8; k++) c += bnb[k] * Watt[k] + bself[k] * Watt[8 + k];
        g_cbias = c;
    }
    if (i == H0 + 1) {
        // edge values < 2^17: if int64 (LE), every odd 32-bit word is 0
        int all0 = 1;
        for (int j = 1; j < 512; j += 2)
            if (eiw[j] != 0u) { all0 = 0; break; }
        g_is64 = all0;
    }
}

// ---------------- edge conversion to packed int2 + degree histogram ----------------
// MUST run before k_gemm (gemm epilogue scales by rsqrt(deg1)).
__global__ void k_cvtdeg(const void* __restrict__ ei) {
    int e = blockIdx.x * blockDim.x + threadIdx.x;
    if (e >= GE) return;
    int r = eidx(ei, e);
    int c = eidx(ei, (long long)GE + e);
    g_eidx[e] = make_int2(r, c);
    atomicAdd(&g_deg1[c], 1.0f);
}

// ---------------- GEMM: xws = (x @ W0) * dinv1[row], tf32 tensor cores -------------
#define SXP 36
#define SWP 33
__global__ __launch_bounds__(128) void k_gemm(const float* __restrict__ x,
                                              const float* __restrict__ W0) {
    __shared__ __align__(16) float sX[256 * SXP];  // 36.9KB (tf32-rounded)
    __shared__ __align__(16) float sW[32 * SWP];   // 4.2KB

    const int tid = threadIdx.x;
    const int lane = tid & 31;
    const int gid = lane >> 2;
    const int tg = lane & 3;
    const int mbase = (tid >> 5) * 64;
    const int rbase = blockIdx.x * 256;

    float c[4][4][4];
#pragma unroll
    for (int mt = 0; mt < 4; mt++)
#pragma unroll
        for (int t = 0; t < 4; t++)
#pragma unroll
            for (int r = 0; r < 4; r++) c[mt][t][r] = 0.f;

    for (int k0 = 0; k0 < 512; k0 += 32) {
#pragma unroll
        for (int i = 0; i < 16; i++) {
            int idx = tid + 128 * i;
            int row = idx >> 3, q = idx & 7;
            int grow = rbase + row;
            if (grow >= GN) grow = GN - 1;
            float4 v = *reinterpret_cast<const float4*>(
                x + (size_t)grow * 512 + k0 + 4 * q);
            v.x = tf32r(v.x); v.y = tf32r(v.y); v.z = tf32r(v.z); v.w = tf32r(v.w);
            *reinterpret_cast<float4*>(&sX[row * SXP + 4 * q]) = v;
        }
#pragma unroll
        for (int i = 0; i < 8; i++) {
            int idx = tid + 128 * i;
            int kk = idx >> 5, cc = idx & 31;
            sW[kk * SWP + cc] = tf32r(W0[(k0 + kk) * H0 + cc]);
        }
        __syncthreads();

#pragma unroll
        for (int kk = 0; kk < 4; kk++) {
            uint32_t b[4][2];
#pragma unroll
            for (int t = 0; t < 4; t++) {
                b[t][0] = __float_as_uint(sW[(kk * 8 + tg) * SWP + t * 8 + gid]);
                b[t][1] = __float_as_uint(sW[(kk * 8 + tg + 4) * SWP + t * 8 + gid]);
            }
#pragma unroll
            for (int mt = 0; mt < 4; mt++) {
                int r0 = mbase + mt * 16;
                uint32_t a0 = __float_as_uint(sX[(r0 + gid) * SXP + kk * 8 + tg]);
                uint32_t a1 = __float_as_uint(sX[(r0 + gid + 8) * SXP + kk * 8 + tg]);
                uint32_t a2 = __float_as_uint(sX[(r0 + gid) * SXP + kk * 8 + tg + 4]);
                uint32_t a3 = __float_as_uint(sX[(r0 + gid + 8) * SXP + kk * 8 + tg + 4]);
#pragma unroll
                for (int t = 0; t < 4; t++)
                    mma_tf32(c[mt][t], a0, a1, a2, a3, b[t][0], b[t][1]);
            }
        }
        __syncthreads();
    }

    // epilogue: scale by dinv1[row] and store
#pragma unroll
    for (int mt = 0; mt < 4; mt++) {
        int r = rbase + mbase + mt * 16 + gid;
        float d0 = (r < GN) ? rsqrtf(g_deg1[r]) : 0.f;
        float d1 = (r + 8 < GN) ? rsqrtf(g_deg1[r + 8]) : 0.f;
#pragma unroll
        for (int t = 0; t < 4; t++) {
            int col = t * 8 + 2 * tg;
            if (r < GN)
                *reinterpret_cast<float2*>(&g_xw[r * H0 + col]) =
                    make_float2(c[mt][t][0] * d0, c[mt][t][1] * d0);
            if (r + 8 < GN)
                *reinterpret_cast<float2*>(&g_xw[(r + 8) * H0 + col]) =
                    make_float2(c[mt][t][2] * d1, c[mt][t][3] * d1);
        }
    }
}

// ---------------- conv1 aggregation: 8 lanes/edge, pure gather+RED ----------------
// xws already carries dinv1[row]; dinv1[col] is applied per-node in k_node.
__global__ __launch_bounds__(256) void k_agg1() {
    long long t = (long long)blockIdx.x * blockDim.x + threadIdx.x;
    if (t >= (long long)GE * 8) return;
    int e = (int)(t >> 3);
    int sub = (int)(t & 7);
    int lane = threadIdx.x & 31;
    int lead = lane & ~7;

    int row = 0, col = 0;
    if ((lane & 7) == 0) {
        int2 rc = g_eidx[e];
        row = rc.x; col = rc.y;
    }
    row = __shfl_sync(0xFFFFFFFFu, row, lead);
    col = __shfl_sync(0xFFFFFFFFu, col, lead);

    float4 v = *reinterpret_cast<const float4*>(&g_xw[row * H0 + sub * 4]);
    red4(&g_hacc[col * H0 + sub * 4], v.x, v.y, v.z, v.w);
}

// ---------------- per-node: h, s1, s2, hw = h @ W1 (warp per node) ----------------
__global__ void k_node(const float* __restrict__ b0, const float* __restrict__ W1) {
    int node = (blockIdx.x * blockDim.x + threadIdx.x) >> 5;
    int lane = threadIdx.x & 31;
    if (node >= GN) return;

    float dn = rsqrtf(g_deg1[node]);   // dinv1[node]
    // hacc = sum of xws[src]; self term xws[node] = xw*dinv1[node]; multiply all by dn
    float h = (g_hacc[node * H0 + lane] + g_xw[node * H0 + lane]) * dn + b0[lane];

    float p1 = h * g_wa1[lane];
    float p2 = h * g_wa2[lane];
#pragma unroll
    for (int o = 16; o; o >>= 1) {
        p1 += __shfl_xor_sync(0xFFFFFFFFu, p1, o);
        p2 += __shfl_xor_sync(0xFFFFFFFFu, p2, o);
    }
    if (lane == 0) { g_s1[node] = p1; g_s2[node] = p2; }

    float4 wA = *reinterpret_cast<const float4*>(W1 + lane * 8);
    float4 wB = *reinterpret_cast<const float4*>(W1 + lane * 8 + 4);
    float o0 = h * wA.x, o1 = h * wA.y, o2 = h * wA.z, o3 = h * wA.w;
    float o4 = h * wB.x, o5 = h * wB.y, o6 = h * wB.z, o7 = h * wB.w;
#pragma unroll
    for (int o = 16; o; o >>= 1) {
        o0 += __shfl_xor_sync(0xFFFFFFFFu, o0, o);
        o1 += __shfl_xor_sync(0xFFFFFFFFu, o1, o);
        o2 += __shfl_xor_sync(0xFFFFFFFFu, o2, o);
        o3 += __shfl_xor_sync(0xFFFFFFFFu, o3, o);
        o4 += __shfl_xor_sync(0xFFFFFFFFu, o4, o);
        o5 += __shfl_xor_sync(0xFFFFFFFFu, o5, o);
        o6 += __shfl_xor_sync(0xFFFFFFFFu, o6, o);
        o7 += __shfl_xor_sync(0xFFFFFFFFu, o7, o);
    }
    if (lane == 0) {
        float4* hw4 = reinterpret_cast<float4*>(&g_hw[node * H1]);
        hw4[0] = make_float4(o0, o1, o2, o3);
        hw4[1] = make_float4(o4, o5, o6, o7);
    }
}

// ---------------- edge gate + deg2 ----------------
__global__ void k_gate() {
    int e = blockIdx.x * blockDim.x + threadIdx.x;
    if (e >= GE) return;
    int2 rc = g_eidx[e];
    float w = g_s1[rc.x] + g_s2[rc.y] + g_cbias;  // pre-relu attention logit
    float mw = 0.f;
    if (w > 0.f) {
        float s = 1.f / (1.f + __expf(-w));       // sigmoid(relu(w)), w>0
        float mask = fminf(s * 1.01f, 1.f);       // clip(s*(zeta-gamma)+gamma, 0, 1)
        mw = mask * w;
        atomicAdd(&g_deg2[rc.y], mw);
    }
    g_mw[e] = mw;
}

// ---------------- oinit: dinv2, out base; scale hw by dinv2 in place --------------
__global__ void k_oinit(float* __restrict__ out, const float* __restrict__ b1) {
    int node = blockIdx.x * blockDim.x + threadIdx.x;
    if (node >= GN) return;
    float d = rsqrtf(g_deg2[node]);
    g_deg2[node] = d;           // dinv2 for agg2
    float dd = d * d;
    float4 hw0 = *reinterpret_cast<const float4*>(&g_hw[node * H1]);
    float4 hw1 = *reinterpret_cast<const float4*>(&g_hw[node * H1 + 4]);
    float4 bA = *reinterpret_cast<const float4*>(b1);
    float4 bB = *reinterpret_cast<const float4*>(b1 + 4);
    // self-loop base uses raw hw
    float4 o0 = make_float4(hw0.x * dd + bA.x, hw0.y * dd + bA.y,
                            hw0.z * dd + bA.z, hw0.w * dd + bA.w);
    float4 o1 = make_float4(hw1.x * dd + bB.x, hw1.y * dd + bB.y,
                            hw1.z * dd + bB.z, hw1.w * dd + bB.w);
    *reinterpret_cast<float4*>(&out[node * H1]) = o0;
    *reinterpret_cast<float4*>(&out[node * H1 + 4]) = o1;
    // scale hw in place for agg2 (hws = hw * dinv2)
    hw0 = make_float4(hw0.x * d, hw0.y * d, hw0.z * d, hw0.w * d);
    hw1 = make_float4(hw1.x * d, hw1.y * d, hw1.z * d, hw1.w * d);
    *reinterpret_cast<float4*>(&g_hw[node * H1]) = hw0;
    *reinterpret_cast<float4*>(&g_hw[node * H1 + 4]) = hw1;
}

// ---------------- conv2 aggregation: 2 threads / edge, RED.128 into d_out ---------
__global__ void k_agg2(float* __restrict__ out) {
    long long t = (long long)blockIdx.x * blockDim.x + threadIdx.x;
    if (t >= (long long)GE * 2) return;
    int e = (int)(t >> 1), q = (int)(t & 1);
    float mw = g_mw[e];
    if (mw == 0.f) return;  // gated off: exact zero contribution
    int2 rc = g_eidx[e];
    float norm = mw * g_deg2[rc.y];   // hw already carries dinv2[row]
    float4 v = *reinterpret_cast<const float4*>(&g_hw[rc.x * H1 + q * 4]);
    red4(&out[rc.y * H1 + q * 4], v.x * norm, v.y * norm, v.z * norm, v.w * norm);
}

// ---------------- launch ----------------
extern "C" void kernel_launch(void* const* d_in, const int* in_sizes, int n_in,
                              void* d_out, int out_size) {
    const float* x   = (const float*)d_in[0];
    const void*  ei  = d_in[1];
    const float* W0  = (const float*)d_in[2];
    const float* b0  = (const float*)d_in[3];
    const float* W1  = (const float*)d_in[4];
    const float* b1  = (const float*)d_in[5];
    const float* Wnb = (const float*)d_in[6];
    const float* bnb = (const float*)d_in[7];
    const float* Wself = (const float*)d_in[8];
    const float* bself = (const float*)d_in[9];
    const float* Watt  = (const float*)d_in[10];
    const float* batt  = (const float*)d_in[11];
    float* out = (float*)d_out;

    k_setup<<<(GN * H0 + 255) / 256, 256>>>((const unsigned int*)ei,
                                            Wnb, bnb, Wself, bself, Watt, batt);
    k_cvtdeg<<<(GE + 255) / 256, 256>>>(ei);     // before gemm: epilogue needs deg1
    k_gemm<<<(GN + 255) / 256, 128>>>(x, W0);
    k_agg1<<<(GE * 8 + 255) / 256, 256>>>();
    k_node<<<(GN * 32 + 255) / 256, 256>>>(b0, W1);
    k_gate<<<(GE + 255) / 256, 256>>>();
    k_oinit<<<(GN + 255) / 256, 256>>>(out, b1);
    k_agg2<<<(GE * 2 + 255) / 256, 256>>>(out);
}